// round 15
// baseline (speedup 1.0000x reference)
#include <cuda_runtime.h>
#include <cstdint>

#define BB 8
#define NN 1024
#define DD 64
#define HH 32

// Interleaved path assignment: 17 MUFU h's spread evenly among 32.
#define IS_MUFU(h) ((((h) + 1) * 17 >> 5) > ((h) * 17 >> 5))

#define N_TILES 2048               // B * 16 * 16
#define GRID_CO 760                // 152 SMs x 5 CTAs (fully resident)

// Scratch (allocation-free rule -> device globals).
__device__ float g_ca[BB * NN * HH];
__device__ float g_dv[BB * NN * HH];
__device__ unsigned int g_ticket;   // dynamic tile ticket (reset each run)
__device__ unsigned int g_done;     // exited CTAs (reset each run)

using u64 = unsigned long long;

__device__ __forceinline__ u64 f2_add(u64 a, u64 b) {
    u64 r; asm("add.rn.f32x2 %0,%1,%2;" : "=l"(r) : "l"(a), "l"(b)); return r;
}
__device__ __forceinline__ u64 f2_mul(u64 a, u64 b) {
    u64 r; asm("mul.rn.f32x2 %0,%1,%2;" : "=l"(r) : "l"(a), "l"(b)); return r;
}
__device__ __forceinline__ u64 f2_fma(u64 a, u64 b, u64 c) {
    u64 r; asm("fma.rn.f32x2 %0,%1,%2,%3;" : "=l"(r) : "l"(a), "l"(b), "l"(c)); return r;
}
__device__ __forceinline__ u64 pack2(float lo, float hi) {
    u64 r; asm("mov.b64 %0,{%1,%2};" : "=l"(r) : "f"(lo), "f"(hi)); return r;
}
__device__ __forceinline__ void unpack2(u64 v, float& lo, float& hi) {
    asm("mov.b64 {%0,%1},%2;" : "=f"(lo), "=f"(hi) : "l"(v));
}
__device__ __forceinline__ float tanh_a(float x) {
    float r; asm("tanh.approx.f32 %0,%1;" : "=f"(r) : "f"(x)); return r;
}

#define ONE2 0x3F8000003F800000ULL

// ---------------------------------------------------------------------------
// Projection v2 (R13, unchanged): 1024 blocks x 16 rows, 256 threads.
// ---------------------------------------------------------------------------
#define ROWS_PB 16
__global__ __launch_bounds__(256) void proj_kernel(
    const float* __restrict__ cell, const float* __restrict__ drug,
    const float* __restrict__ w_q, const float* __restrict__ w_k,
    const float* __restrict__ bias)
{
    __shared__ float s_x[ROWS_PB][68];
    __shared__ float s_w[DD][HH];

    int tid = threadIdx.x;
    int blk = blockIdx.x;
    const int blocks_per_side = (BB * NN) / ROWS_PB; // 512
    bool is_drug = blk >= blocks_per_side;
    int row0 = (is_drug ? blk - blocks_per_side : blk) * ROWS_PB;
    const float* src = (is_drug ? drug : cell) + (size_t)row0 * DD;
    const float* W   = is_drug ? w_q : w_k;

    {
        int row = tid >> 4, d4 = tid & 15;
        float4 v = *reinterpret_cast<const float4*>(src + row * DD + d4 * 4);
        *reinterpret_cast<float4*>(&s_x[row][d4 * 4]) = v;
    }
#pragma unroll
    for (int k = 0; k < 2; k++) {
        int idx = tid + k * 256;
        *reinterpret_cast<float4*>(reinterpret_cast<float*>(s_w) + idx * 4) =
            *reinterpret_cast<const float4*>(W + idx * 4);
    }
    __syncthreads();

    int hp  = tid & 15;
    int row = tid >> 4;

    float a0 = 0.f, a1 = 0.f;
#pragma unroll
    for (int d = 0; d < DD; d++) {
        float x = s_x[row][d];
        float2 w2 = *reinterpret_cast<float2*>(&s_w[d][hp * 2]);
        a0 = fmaf(x, w2.x, a0);
        a1 = fmaf(x, w2.y, a1);
    }

    int h0 = hp * 2;
    if (is_drug) {
        float2 b2 = *reinterpret_cast<const float2*>(bias + h0);
        a0 += b2.x; a1 += b2.y;
    }
    if (!IS_MUFU(h0))     a0 = tanh_a(a0);
    if (!IS_MUFU(h0 + 1)) a1 = tanh_a(a1);

    float* dst = (is_drug ? g_dv : g_ca) + (size_t)(row0 + row) * HH + h0;
    *reinterpret_cast<float2*>(dst) = make_float2(a0, a1);
}

// ---------------------------------------------------------------------------
// Co-attention, persistent + dynamic ticket. Tile body identical to R13.
// Next ticket grabbed at compute start (latency hidden); consumed after the
// end barrier. Counters reset by the last exiting CTA (replay-safe).
// ---------------------------------------------------------------------------
__global__ __launch_bounds__(256, 5) void coattn_kernel(
    const float* __restrict__ a_vec, float* __restrict__ out)
{
    __shared__ float s_u[64][36];
    __shared__ float s_v[HH][68];
    __shared__ u64   s_a2[HH];
    __shared__ unsigned int s_t;

    int tid = threadIdx.x;

    // Stage a2 once per CTA (input-only).
    if (tid < HH) {
        float av = a_vec[tid];
        if (!IS_MUFU(tid)) av = -av;   // folds r = -s*z sign on Newton path
        s_a2[tid] = pack2(av, av);
    }

    cudaGridDependencySynchronize();   // g_ca/g_dv ready (PDL)

    if (tid == 0) s_t = atomicAdd(&g_ticket, 1u);
    __syncthreads();
    unsigned int t = s_t;

    int tx = tid & 15;        // j quad (4 consecutive cols -> float4 store)
    int ty = tid >> 4;        // i quad

    while (t < (unsigned)N_TILES) {
        int jx = t & 15;
        int iy = (t >> 4) & 15;
        int b  = t >> 8;
        int i0 = iy * 64, j0 = jx * 64;

        const float* ca = g_ca + (b * NN + i0) * HH;
        const float* dv = g_dv + (b * NN + j0) * HH;

#pragma unroll
        for (int k = 0; k < 2; k++) {
            int idx = tid + k * 256;       // 0..511
            int row = idx >> 3, g = idx & 7;
            float4 uu = *reinterpret_cast<const float4*>(ca + row * HH + 4 * g);
            *reinterpret_cast<float4*>(&s_u[row][4 * g]) = uu;
            float4 vv = *reinterpret_cast<const float4*>(dv + row * HH + 4 * g);
            s_v[4 * g + 0][row] = vv.x;
            s_v[4 * g + 1][row] = vv.y;
            s_v[4 * g + 2][row] = vv.z;
            s_v[4 * g + 3][row] = vv.w;
        }
        __syncthreads();

        // Grab next ticket early; latency hidden under compute. s_t is only
        // read after the end barrier below.
        if (tid == 0) s_t = atomicAdd(&g_ticket, 1u);

        u64 acc[4][2];
#pragma unroll
        for (int r = 0; r < 4; r++) { acc[r][0] = 0ULL; acc[r][1] = 0ULL; }

#pragma unroll
        for (int g = 0; g < 16; g++) {                // h-groups of 2
            float2 u2r[4];
#pragma unroll
            for (int r = 0; r < 4; r++)
                u2r[r] = *reinterpret_cast<float2*>(&s_u[ty * 4 + r][2 * g]);

#pragma unroll
            for (int k = 0; k < 2; k++) {
                const int h = 2 * g + k;              // compile-time
                float4 vv = *reinterpret_cast<float4*>(&s_v[h][tx * 4]);
                u64 v2[2] = { pack2(vv.x, vv.y), pack2(vv.z, vv.w) };
                u64 a2 = s_a2[h];

#pragma unroll
                for (int r = 0; r < 4; r++) {
                    float us = k ? u2r[r].y : u2r[r].x;
                    u64 up = pack2(us, us);
#pragma unroll
                    for (int cp = 0; cp < 2; cp++) {
                        u64 s2 = f2_add(up, v2[cp]);
                        if (IS_MUFU(h)) {
                            float lo, hi; unpack2(s2, lo, hi);
                            u64 t2 = pack2(tanh_a(lo), tanh_a(hi));
                            acc[r][cp] = f2_fma(a2, t2, acc[r][cp]);
                        } else {
                            u64 d2 = f2_fma(up, v2[cp], ONE2);      // d = 1+tu*tv
                            float dl, dh; unpack2(d2, dl, dh);
                            u64 z = pack2(                           // z0 ~ -1/d seed
                                __uint_as_float(0xFEF311C3u - __float_as_uint(dl)),
                                __uint_as_float(0xFEF311C3u - __float_as_uint(dh)));
                            u64 e = f2_fma(d2, z, ONE2);             // e = 1 + d*z
                            u64 p = f2_fma(e, e, e);                 // e + e^2
                            z     = f2_fma(z, p, z);                 // -1/d, err e^3
                            u64 pp = f2_mul(s2, z);                  // -s/d
                            acc[r][cp] = f2_fma(a2, pp, acc[r][cp]); // a2 pre-negated
                        }
                    }
                }
            }
        }

#pragma unroll
        for (int r = 0; r < 4; r++) {
            float o0, o1, o2, o3;
            unpack2(acc[r][0], o0, o1);
            unpack2(acc[r][1], o2, o3);
            int i = i0 + ty * 4 + r;
            *reinterpret_cast<float4*>(out + ((size_t)b * NN + i) * NN + j0 + tx * 4) =
                make_float4(o0, o1, o2, o3);
        }

        __syncthreads();          // smem WAR for restage; s_t visible to all
        t = s_t;
    }

    // Reset protocol: last CTA to exit resets counters. All CTAs are past
    // their final ticket read; replays are stream-sequential.
    if (tid == 0) {
        unsigned int o = atomicAdd(&g_done, 1u);
        if (o == (unsigned)(GRID_CO - 1)) {
            g_ticket = 0u;
            g_done   = 0u;
            __threadfence();
        }
    }
}

extern "C" void kernel_launch(void* const* d_in, const int* in_sizes, int n_in,
                              void* d_out, int out_size)
{
    const float* cell = (const float*)d_in[0];
    const float* drug = (const float*)d_in[1];
    const float* w_q  = (const float*)d_in[2];
    const float* w_k  = (const float*)d_in[3];
    const float* bias = (const float*)d_in[4];
    const float* a    = (const float*)d_in[5];
    float* out = (float*)d_out;

    proj_kernel<<<2 * (BB * NN) / ROWS_PB, 256>>>(cell, drug, w_q, w_k, bias);

    cudaLaunchConfig_t cfg = {};
    cfg.gridDim  = dim3(GRID_CO, 1, 1);
    cfg.blockDim = dim3(256, 1, 1);
    cfg.dynamicSmemBytes = 0;
    cfg.stream = 0;
    cudaLaunchAttribute attrs[1];
    attrs[0].id = cudaLaunchAttributeProgrammaticStreamSerialization;
    attrs[0].val.programmaticStreamSerializationAllowed = 1;
    cfg.attrs = attrs;
    cfg.numAttrs = 1;
    cudaLaunchKernelEx(&cfg, coattn_kernel, a, out);
}

// round 16
// speedup vs baseline: 1.0354x; 1.0354x over previous
#include <cuda_runtime.h>
#include <cstdint>

#define BB 8
#define NN 1024
#define DD 64
#define HH 32

// Path split: even h = MUFU (raw stored), odd h = Newton (tanh stored).
// Strictly alternating so a runtime group-rotation keeps path selection
// compile-time (k=0 -> MUFU, k=1 -> Newton).

// Scratch (allocation-free rule -> device globals).
__device__ float g_ca[BB * NN * HH];
__device__ float g_dv[BB * NN * HH];

using u64 = unsigned long long;

__device__ __forceinline__ u64 f2_add(u64 a, u64 b) {
    u64 r; asm("add.rn.f32x2 %0,%1,%2;" : "=l"(r) : "l"(a), "l"(b)); return r;
}
__device__ __forceinline__ u64 f2_mul(u64 a, u64 b) {
    u64 r; asm("mul.rn.f32x2 %0,%1,%2;" : "=l"(r) : "l"(a), "l"(b)); return r;
}
__device__ __forceinline__ u64 f2_fma(u64 a, u64 b, u64 c) {
    u64 r; asm("fma.rn.f32x2 %0,%1,%2,%3;" : "=l"(r) : "l"(a), "l"(b), "l"(c)); return r;
}
__device__ __forceinline__ u64 pack2(float lo, float hi) {
    u64 r; asm("mov.b64 %0,{%1,%2};" : "=l"(r) : "f"(lo), "f"(hi)); return r;
}
__device__ __forceinline__ void unpack2(u64 v, float& lo, float& hi) {
    asm("mov.b64 {%0,%1},%2;" : "=f"(lo), "=f"(hi) : "l"(v));
}
__device__ __forceinline__ float tanh_a(float x) {
    float r; asm("tanh.approx.f32 %0,%1;" : "=f"(r) : "f"(x)); return r;
}

#define ONE2 0x3F8000003F800000ULL

// ---------------------------------------------------------------------------
// Projection (R13 v2): 1024 blocks x 16 rows, 256 threads. Each thread: 1 row,
// 2 consecutive h (even=raw, odd=tanh'd).
// ---------------------------------------------------------------------------
#define ROWS_PB 16
__global__ __launch_bounds__(256) void proj_kernel(
    const float* __restrict__ cell, const float* __restrict__ drug,
    const float* __restrict__ w_q, const float* __restrict__ w_k,
    const float* __restrict__ bias)
{
    __shared__ float s_x[ROWS_PB][68];
    __shared__ float s_w[DD][HH];

    int tid = threadIdx.x;
    int blk = blockIdx.x;
    const int blocks_per_side = (BB * NN) / ROWS_PB; // 512
    bool is_drug = blk >= blocks_per_side;
    int row0 = (is_drug ? blk - blocks_per_side : blk) * ROWS_PB;
    const float* src = (is_drug ? drug : cell) + (size_t)row0 * DD;
    const float* W   = is_drug ? w_q : w_k;

    {
        int row = tid >> 4, d4 = tid & 15;
        float4 v = *reinterpret_cast<const float4*>(src + row * DD + d4 * 4);
        *reinterpret_cast<float4*>(&s_x[row][d4 * 4]) = v;
    }
#pragma unroll
    for (int k = 0; k < 2; k++) {
        int idx = tid + k * 256;
        *reinterpret_cast<float4*>(reinterpret_cast<float*>(s_w) + idx * 4) =
            *reinterpret_cast<const float4*>(W + idx * 4);
    }
    __syncthreads();

    int hp  = tid & 15;      // h-pair: h = hp*2 (even), hp*2+1 (odd)
    int row = tid >> 4;      // 0..15

    float a0 = 0.f, a1 = 0.f;
#pragma unroll
    for (int d = 0; d < DD; d++) {
        float x = s_x[row][d];
        float2 w2 = *reinterpret_cast<float2*>(&s_w[d][hp * 2]);
        a0 = fmaf(x, w2.x, a0);
        a1 = fmaf(x, w2.y, a1);
    }

    int h0 = hp * 2;
    if (is_drug) {
        float2 b2 = *reinterpret_cast<const float2*>(bias + h0);
        a0 += b2.x; a1 += b2.y;
    }
    a1 = tanh_a(a1);             // odd h = Newton path: store tanh'd

    float* dst = (is_drug ? g_dv : g_ca) + (size_t)(row0 + row) * HH + h0;
    *reinterpret_cast<float2*>(dst) = make_float2(a0, a1);
}

// ---------------------------------------------------------------------------
// Co-attention: R13 body + per-warp rotation of the h-group loop. Each warp
// starts at group offset 2*wid (mod 16) so co-resident warps occupy different
// (MUFU, Newton) phases and both pipes stay loaded.
// k=0 (even h): t = tanh.approx(u+v) on MUFU; acc += a*t
// k=1 (odd h):  tanh(u+v) = (tu+tv)/(1+tu*tv); rcp = bit-seed + fused cubic
//               correction z*(1+e+e^2) on the FMA pipe (a pre-negated).
// ---------------------------------------------------------------------------
__global__ __launch_bounds__(256, 5) void coattn_kernel(
    const float* __restrict__ a_vec, float* __restrict__ out)
{
    __shared__ float s_u[64][36];      // [i-row][h], padded (16B-aligned rows)
    __shared__ float s_v[HH][68];      // [h][j-col] transposed, padded
    __shared__ u64   s_a2[HH];         // (a_h, a_h), negated for odd h

    int b  = blockIdx.z;
    int i0 = blockIdx.y * 64;
    int j0 = blockIdx.x * 64;
    int tid = threadIdx.x;

    // Independent preamble (inputs only, no proj dependency).
    if (tid < HH) {
        float av = a_vec[tid];
        if (tid & 1) av = -av;         // folds r = -s*z sign on Newton path
        s_a2[tid] = pack2(av, av);
    }

    const float* ca = g_ca + (b * NN + i0) * HH;
    const float* dv = g_dv + (b * NN + j0) * HH;

    // Wait for proj_kernel's writes to g_ca/g_dv to be visible.
    cudaGridDependencySynchronize();

#pragma unroll
    for (int k = 0; k < 2; k++) {
        int idx = tid + k * 256;       // 0..511
        int row = idx >> 3, g = idx & 7;
        float4 uu = *reinterpret_cast<const float4*>(ca + row * HH + 4 * g);
        *reinterpret_cast<float4*>(&s_u[row][4 * g]) = uu;
        float4 vv = *reinterpret_cast<const float4*>(dv + row * HH + 4 * g);
        s_v[4 * g + 0][row] = vv.x;
        s_v[4 * g + 1][row] = vv.y;
        s_v[4 * g + 2][row] = vv.z;
        s_v[4 * g + 3][row] = vv.w;
    }
    __syncthreads();

    int tx = tid & 15;        // j quad (4 consecutive cols -> float4 store)
    int ty = tid >> 4;        // i quad
    int rot = ((tid >> 5) & 7) << 1;   // per-warp group rotation: 0,2,..,14

    u64 acc[4][2];
#pragma unroll
    for (int r = 0; r < 4; r++) { acc[r][0] = 0ULL; acc[r][1] = 0ULL; }

#pragma unroll
    for (int g0 = 0; g0 < 16; g0++) {             // h-groups of 2, rotated
        int g = (g0 + rot) & 15;                  // runtime group index
        float2 u2r[4];
#pragma unroll
        for (int r = 0; r < 4; r++)
            u2r[r] = *reinterpret_cast<float2*>(&s_u[ty * 4 + r][2 * g]);

#pragma unroll
        for (int k = 0; k < 2; k++) {             // k=0: MUFU, k=1: Newton
            int h = 2 * g + k;                    // runtime (addressing only)
            float4 vv = *reinterpret_cast<float4*>(&s_v[h][tx * 4]);
            u64 v2[2] = { pack2(vv.x, vv.y), pack2(vv.z, vv.w) };
            u64 a2 = s_a2[h];

#pragma unroll
            for (int r = 0; r < 4; r++) {
                float us = k ? u2r[r].y : u2r[r].x;
                u64 up = pack2(us, us);
#pragma unroll
                for (int cp = 0; cp < 2; cp++) {
                    u64 s2 = f2_add(up, v2[cp]);
                    if (k == 0) {                 // MUFU path (even h)
                        float lo, hi; unpack2(s2, lo, hi);
                        u64 t2 = pack2(tanh_a(lo), tanh_a(hi));
                        acc[r][cp] = f2_fma(a2, t2, acc[r][cp]);
                    } else {                      // Newton path (odd h)
                        u64 d2 = f2_fma(up, v2[cp], ONE2);          // d = 1+tu*tv
                        float dl, dh; unpack2(d2, dl, dh);
                        u64 z = pack2(                               // z0 ~ -1/d seed
                            __uint_as_float(0xFEF311C3u - __float_as_uint(dl)),
                            __uint_as_float(0xFEF311C3u - __float_as_uint(dh)));
                        u64 e = f2_fma(d2, z, ONE2);                 // e = 1 + d*z
                        u64 p = f2_fma(e, e, e);                     // e + e^2
                        z     = f2_fma(z, p, z);                     // -1/d, err e^3
                        u64 pp = f2_mul(s2, z);                      // -s/d
                        acc[r][cp] = f2_fma(a2, pp, acc[r][cp]);     // a2 pre-negated
                    }
                }
            }
        }
    }

    // Stores come straight from the j-packed accumulators.
#pragma unroll
    for (int r = 0; r < 4; r++) {
        float o0, o1, o2, o3;
        unpack2(acc[r][0], o0, o1);
        unpack2(acc[r][1], o2, o3);
        int i = i0 + ty * 4 + r;
        *reinterpret_cast<float4*>(out + ((size_t)b * NN + i) * NN + j0 + tx * 4) =
            make_float4(o0, o1, o2, o3);
    }
}

extern "C" void kernel_launch(void* const* d_in, const int* in_sizes, int n_in,
                              void* d_out, int out_size)
{
    const float* cell = (const float*)d_in[0];
    const float* drug = (const float*)d_in[1];
    const float* w_q  = (const float*)d_in[2];
    const float* w_k  = (const float*)d_in[3];
    const float* bias = (const float*)d_in[4];
    const float* a    = (const float*)d_in[5];
    float* out = (float*)d_out;

    proj_kernel<<<2 * (BB * NN) / ROWS_PB, 256>>>(cell, drug, w_q, w_k, bias);

    // Co-attention with programmatic dependent launch.
    cudaLaunchConfig_t cfg = {};
    cfg.gridDim  = dim3(NN / 64, NN / 64, BB);
    cfg.blockDim = dim3(256, 1, 1);
    cfg.dynamicSmemBytes = 0;
    cfg.stream = 0;
    cudaLaunchAttribute attrs[1];
    attrs[0].id = cudaLaunchAttributeProgrammaticStreamSerialization;
    attrs[0].val.programmaticStreamSerializationAllowed = 1;
    cfg.attrs = attrs;
    cfg.numAttrs = 1;
    cudaLaunchKernelEx(&cfg, coattn_kernel, a, out);
}

// round 17
// speedup vs baseline: 1.0559x; 1.0198x over previous
#include <cuda_runtime.h>
#include <cstdint>

#define BB 8
#define NN 1024
#define DD 64
#define HH 32

// Split: h % 4 == 3 -> NE (exp-Newton, proj stores e^{2u}); else T32 (MUFU
// tanh, proj stores raw). 24 T32 / 8 NE, interleaved.
#define IS_NE(h) (((h) & 3) == 3)

// Scratch (allocation-free rule -> device globals).
__device__ float g_ca[BB * NN * HH];
__device__ float g_dv[BB * NN * HH];

using u64 = unsigned long long;

__device__ __forceinline__ u64 f2_add(u64 a, u64 b) {
    u64 r; asm("add.rn.f32x2 %0,%1,%2;" : "=l"(r) : "l"(a), "l"(b)); return r;
}
__device__ __forceinline__ u64 f2_mul(u64 a, u64 b) {
    u64 r; asm("mul.rn.f32x2 %0,%1,%2;" : "=l"(r) : "l"(a), "l"(b)); return r;
}
__device__ __forceinline__ u64 f2_fma(u64 a, u64 b, u64 c) {
    u64 r; asm("fma.rn.f32x2 %0,%1,%2,%3;" : "=l"(r) : "l"(a), "l"(b), "l"(c)); return r;
}
__device__ __forceinline__ u64 pack2(float lo, float hi) {
    u64 r; asm("mov.b64 %0,{%1,%2};" : "=l"(r) : "f"(lo), "f"(hi)); return r;
}
__device__ __forceinline__ void unpack2(u64 v, float& lo, float& hi) {
    asm("mov.b64 {%0,%1},%2;" : "=f"(lo), "=f"(hi) : "l"(v));
}
__device__ __forceinline__ float tanh_a(float x) {
    float r; asm("tanh.approx.f32 %0,%1;" : "=f"(r) : "f"(x)); return r;
}
__device__ __forceinline__ float ex2_a(float x) {
    float r; asm("ex2.approx.f32 %0,%1;" : "=f"(r) : "f"(x)); return r;
}
__device__ __forceinline__ float rcp_seed(float d) {   // ~ -1/d
    return __uint_as_float(0xFEF311C3u - __float_as_uint(d));
}

#define ONE2 0x3F8000003F800000ULL
#define LOG2E_X2 2.8853900817779268f

// ---------------------------------------------------------------------------
// Projection (R13 v2 structure): 1024 blocks x 16 rows, 256 threads.
// Each thread: 1 row, 2 consecutive h. T32-h stores raw; NE-h (h%4==3)
// stores e^{2u} via ex2 (argument clamped so E=Eu*Ev stays finite/normal).
// ---------------------------------------------------------------------------
#define ROWS_PB 16
__global__ __launch_bounds__(256) void proj_kernel(
    const float* __restrict__ cell, const float* __restrict__ drug,
    const float* __restrict__ w_q, const float* __restrict__ w_k,
    const float* __restrict__ bias)
{
    __shared__ float s_x[ROWS_PB][68];
    __shared__ float s_w[DD][HH];

    int tid = threadIdx.x;
    int blk = blockIdx.x;
    const int blocks_per_side = (BB * NN) / ROWS_PB; // 512
    bool is_drug = blk >= blocks_per_side;
    int row0 = (is_drug ? blk - blocks_per_side : blk) * ROWS_PB;
    const float* src = (is_drug ? drug : cell) + (size_t)row0 * DD;
    const float* W   = is_drug ? w_q : w_k;

    {
        int row = tid >> 4, d4 = tid & 15;
        float4 v = *reinterpret_cast<const float4*>(src + row * DD + d4 * 4);
        *reinterpret_cast<float4*>(&s_x[row][d4 * 4]) = v;
    }
#pragma unroll
    for (int k = 0; k < 2; k++) {
        int idx = tid + k * 256;
        *reinterpret_cast<float4*>(reinterpret_cast<float*>(s_w) + idx * 4) =
            *reinterpret_cast<const float4*>(W + idx * 4);
    }
    __syncthreads();

    int hp  = tid & 15;      // h-pair: h = hp*2 (even, T32), hp*2+1 (odd)
    int row = tid >> 4;      // 0..15

    float a0 = 0.f, a1 = 0.f;
#pragma unroll
    for (int d = 0; d < DD; d++) {
        float x = s_x[row][d];
        float2 w2 = *reinterpret_cast<float2*>(&s_w[d][hp * 2]);
        a0 = fmaf(x, w2.x, a0);
        a1 = fmaf(x, w2.y, a1);
    }

    int h0 = hp * 2;
    if (is_drug) {
        float2 b2 = *reinterpret_cast<const float2*>(bias + h0);
        a0 += b2.x; a1 += b2.y;
    }
    // Even h always T32 (raw). Odd h: NE if (h0+1)%4==3.
    if (((h0 + 1) & 3) == 3) {
        float x = fminf(63.f, fmaxf(-63.f, LOG2E_X2 * a1));
        a1 = ex2_a(x);                      // e^{2u}, normal-range guaranteed
    }

    float* dst = (is_drug ? g_dv : g_ca) + (size_t)(row0 + row) * HH + h0;
    *reinterpret_cast<float2*>(dst) = make_float2(a0, a1);
}

// ---------------------------------------------------------------------------
// Co-attention: 64x64 tile/CTA, 4x4 outputs/thread, accumulators packed over
// j (4x2 f32x2). h-groups of 2; within each group k=0 is T32; k=1 is T32 for
// even g, NE for odd g (h%4==3).
// T32: t = tanh.approx(u+v) on MUFU;                       acc += a*t
// NE:  tanh(u+v) = 1 - 2/(Eu*Ev+1); acc += 2a*z, z=-1/d via bit-seed + fused
//      cubic correction on the FMA pipe; the "+a" parts pre-summed into the
//      accumulator init (S = sum of NE a_h). 6 FMA ops, no MUFU.
// ---------------------------------------------------------------------------
__global__ __launch_bounds__(256, 5) void coattn_kernel(
    const float* __restrict__ a_vec, float* __restrict__ out)
{
    __shared__ float s_u[64][36];      // [i-row][h], padded (16B-aligned rows)
    __shared__ float s_v[HH][68];      // [h][j-col] transposed, padded
    __shared__ u64   s_a2[HH];         // (a,a) for T32; (2a,2a) for NE

    int b  = blockIdx.z;
    int i0 = blockIdx.y * 64;
    int j0 = blockIdx.x * 64;
    int tid = threadIdx.x;

    // Independent preamble (inputs only, no proj dependency).
    if (tid < HH) {
        float av = a_vec[tid];
        if (IS_NE(tid)) av *= 2.0f;    // NE contribution is a + 2a*z
        s_a2[tid] = pack2(av, av);
    }
    // S = sum of a_h over NE h's (constant part of NE contributions).
    float S = 0.f;
#pragma unroll
    for (int h = 3; h < HH; h += 4) S += a_vec[h];
    u64 S2 = pack2(S, S);

    const float* ca = g_ca + (b * NN + i0) * HH;
    const float* dv = g_dv + (b * NN + j0) * HH;

    // Wait for proj_kernel's writes to g_ca/g_dv to be visible (PDL).
    cudaGridDependencySynchronize();

#pragma unroll
    for (int k = 0; k < 2; k++) {
        int idx = tid + k * 256;       // 0..511
        int row = idx >> 3, g = idx & 7;
        float4 uu = *reinterpret_cast<const float4*>(ca + row * HH + 4 * g);
        *reinterpret_cast<float4*>(&s_u[row][4 * g]) = uu;
        float4 vv = *reinterpret_cast<const float4*>(dv + row * HH + 4 * g);
        s_v[4 * g + 0][row] = vv.x;
        s_v[4 * g + 1][row] = vv.y;
        s_v[4 * g + 2][row] = vv.z;
        s_v[4 * g + 3][row] = vv.w;
    }
    __syncthreads();

    int tx = tid & 15;        // j quad (4 consecutive cols -> float4 store)
    int ty = tid >> 4;        // i quad

    u64 acc[4][2];
#pragma unroll
    for (int r = 0; r < 4; r++) { acc[r][0] = S2; acc[r][1] = S2; }

#pragma unroll
    for (int g = 0; g < 16; g++) {                // h-groups of 2
        float2 u2r[4];
#pragma unroll
        for (int r = 0; r < 4; r++)
            u2r[r] = *reinterpret_cast<float2*>(&s_u[ty * 4 + r][2 * g]);

#pragma unroll
        for (int k = 0; k < 2; k++) {
            const int h = 2 * g + k;              // compile-time
            const bool is_ne = (k == 1) && ((g & 1) == 1);   // h%4==3
            float4 vv = *reinterpret_cast<float4*>(&s_v[h][tx * 4]);
            u64 v2[2] = { pack2(vv.x, vv.y), pack2(vv.z, vv.w) };
            u64 a2 = s_a2[h];

#pragma unroll
            for (int r = 0; r < 4; r++) {
                float us = k ? u2r[r].y : u2r[r].x;
                u64 up = pack2(us, us);
#pragma unroll
                for (int cp = 0; cp < 2; cp++) {
                    if (!is_ne) {                 // T32: MUFU tanh
                        u64 s2 = f2_add(up, v2[cp]);
                        float lo, hi; unpack2(s2, lo, hi);
                        u64 t2 = pack2(tanh_a(lo), tanh_a(hi));
                        acc[r][cp] = f2_fma(a2, t2, acc[r][cp]);
                    } else {                      // NE: exp-Newton, 6 FMA ops
                        u64 E2 = f2_mul(up, v2[cp]);        // Eu*Ev = e^{2(u+v)}
                        u64 d2 = f2_add(E2, ONE2);          // d = E+1 (>1)
                        float dl, dh; unpack2(d2, dl, dh);
                        u64 z = pack2(rcp_seed(dl), rcp_seed(dh));  // ~ -1/d
                        u64 e = f2_fma(d2, z, ONE2);        // e = 1 + d*z
                        u64 p = f2_fma(e, e, e);            // e + e^2
                        z     = f2_fma(z, p, z);            // -1/d, err ~ e^3
                        acc[r][cp] = f2_fma(a2, z, acc[r][cp]);  // += 2a*z
                    }
                }
            }
        }
    }

    // Stores come straight from the j-packed accumulators.
#pragma unroll
    for (int r = 0; r < 4; r++) {
        float o0, o1, o2, o3;
        unpack2(acc[r][0], o0, o1);
        unpack2(acc[r][1], o2, o3);
        int i = i0 + ty * 4 + r;
        *reinterpret_cast<float4*>(out + ((size_t)b * NN + i) * NN + j0 + tx * 4) =
            make_float4(o0, o1, o2, o3);
    }
}

extern "C" void kernel_launch(void* const* d_in, const int* in_sizes, int n_in,
                              void* d_out, int out_size)
{
    const float* cell = (const float*)d_in[0];
    const float* drug = (const float*)d_in[1];
    const float* w_q  = (const float*)d_in[2];
    const float* w_k  = (const float*)d_in[3];
    const float* bias = (const float*)d_in[4];
    const float* a    = (const float*)d_in[5];
    float* out = (float*)d_out;

    proj_kernel<<<2 * (BB * NN) / ROWS_PB, 256>>>(cell, drug, w_q, w_k, bias);

    // Co-attention with programmatic dependent launch.
    cudaLaunchConfig_t cfg = {};
    cfg.gridDim  = dim3(NN / 64, NN / 64, BB);
    cfg.blockDim = dim3(256, 1, 1);
    cfg.dynamicSmemBytes = 0;
    cfg.stream = 0;
    cudaLaunchAttribute attrs[1];
    attrs[0].id = cudaLaunchAttributeProgrammaticStreamSerialization;
    attrs[0].val.programmaticStreamSerializationAllowed = 1;
    cfg.attrs = attrs;
    cfg.numAttrs = 1;
    cudaLaunchKernelEx(&cfg, coattn_kernel, a, out);
}